// round 8
// baseline (speedup 1.0000x reference)
#include <cuda_runtime.h>
#include <math.h>
#include <stdint.h>

// Problem constants
#define TSEQ 2048
#define NHEAD 16
#define HDIM 128
// mask: keep k < 204 or k >= 1229 ; evict = 1229 ; recent rb = 819
// last_start = 1792 ; mean over k in [1230, 2048) -> 818 elements

// ---------------- scratch (static device globals; no allocation) -------------
__device__ float g_q[NHEAD * TSEQ * HDIM];   // [h][t][d], rope applied
__device__ float g_k[NHEAD * TSEQ * HDIM];
__device__ float g_v[NHEAD * TSEQ * HDIM];
__device__ float g_ctx[TSEQ * 2048];         // [t][h*128+d]
__device__ float g_ve[NHEAD * HDIM];         // v_e per head (includes bern/rb)

// nan_to_num(nan=0, posinf=1e4, neginf=-1e4): replaces non-finite ONLY
__device__ __forceinline__ float nn_fix(float x) {
    if (isnan(x)) return 0.0f;
    if (isinf(x)) return x > 0.0f ? 10000.0f : -10000.0f;
    return x;
}

__device__ __forceinline__ float tf32rna(float x) {
    float r;
    asm("cvt.rna.tf32.f32 %0, %1;" : "=f"(r) : "f"(x));
    return r;
}

// portable (non-'a') tensor core: mma.sync m16n8k8 tf32, fp32 accumulate
__device__ __forceinline__ void mma_tf32(float* d, const uint32_t* a,
                                         const uint32_t* b) {
    asm volatile(
        "mma.sync.aligned.m16n8k8.row.col.f32.tf32.tf32.f32 "
        "{%0,%1,%2,%3}, {%4,%5,%6,%7}, {%8,%9}, {%0,%1,%2,%3};"
        : "+f"(d[0]), "+f"(d[1]), "+f"(d[2]), "+f"(d[3])
        : "r"(a[0]), "r"(a[1]), "r"(a[2]), "r"(a[3]), "r"(b[0]), "r"(b[1]));
}

// ============ mma.sync TF32x3 GEMM: C[M,N] = A[M,K] * B[N,K]^T ===============
// M=N=K=2048, CTA tile 128x128, 256 threads (8 warps, 2x4), warp tile 64x32.
// SMEM chunk: 32 K-columns; hi/lo tiles stored with (k, k+4) pairs adjacent so
// every fragment load is a single LDS.64.
// Layout: X_s[row][ks*8 + 2*j + b] = X[row][ks*8 + j + 4*b], row stride 34.
#define G_LDS 34
#define G_TILE_FLOATS (128 * G_LDS)
#define G_SMEM_FLOATS (4 * G_TILE_FLOATS)   // Ah, Al, Bh, Bl
#define G_SMEM_BYTES  (G_SMEM_FLOATS * 4)

__global__ void __launch_bounds__(256, 1)
gemm_tc_kernel(const float* __restrict__ Aext, const float* __restrict__ B,
               float* __restrict__ Cext, int mode)
{
    extern __shared__ float gsm[];
    float* Ah_s = gsm;
    float* Al_s = Ah_s + G_TILE_FLOATS;
    float* Bh_s = Al_s + G_TILE_FLOATS;
    float* Bl_s = Bh_s + G_TILE_FLOATS;

    const float* A = (mode == 3) ? (const float*)g_ctx : Aext;
    const bool fixA = (mode != 3);

    const int tid  = threadIdx.x;
    const int wid  = tid >> 5;
    const int lane = tid & 31;
    const int g    = lane >> 2;     // group 0..7
    const int tig  = lane & 3;      // thread in group 0..3
    const int bm = blockIdx.y, bn = blockIdx.x;

    const int warp_m = (wid >> 2) * 64;   // 0 or 64
    const int warp_n = (wid & 3) * 32;    // 0,32,64,96

    // C fragments: 4 m-tiles x 4 n-tiles x 4 regs
    float c[4][4][4];
#pragma unroll
    for (int i = 0; i < 4; ++i)
#pragma unroll
        for (int j = 0; j < 4; ++j)
#pragma unroll
            for (int q = 0; q < 4; ++q) c[i][j][q] = 0.0f;

    const float* Ab = A + (size_t)(bm * 128) * 2048;
    const float* Bb = B + (size_t)(bn * 128) * 2048;

    // GMEM load assignment: row = tid>>1, k half = (tid&1)*16
    const int gr = tid >> 1;
    const int gk = (tid & 1) * 16;

    float4 apf[4], bpf[4];
    // prefetch chunk 0
#pragma unroll
    for (int i = 0; i < 4; ++i) {
        apf[i] = *(const float4*)(Ab + (size_t)gr * 2048 + gk + i * 4);
        bpf[i] = *(const float4*)(Bb + (size_t)gr * 2048 + gk + i * 4);
    }

    for (int ch = 0; ch < 64; ++ch) {
        // ---- split + store prefetched chunk to SMEM (interleaved pairs) ----
#pragma unroll
        for (int half = 0; half < 2; ++half) {
            float4 va = apf[half * 2], vb = apf[half * 2 + 1]; // k.. k+3, k+4..k+7
            if (fixA) {
                va.x = nn_fix(va.x); va.y = nn_fix(va.y);
                va.z = nn_fix(va.z); va.w = nn_fix(va.w);
                vb.x = nn_fix(vb.x); vb.y = nn_fix(vb.y);
                vb.z = nn_fix(vb.z); vb.w = nn_fix(vb.w);
            }
            const int base = gr * G_LDS + gk + half * 8;
            float lo0[4] = { va.x, va.y, va.z, va.w };
            float lo4[4] = { vb.x, vb.y, vb.z, vb.w };
#pragma unroll
            for (int j = 0; j < 4; ++j) {
                const float h0 = tf32rna(lo0[j]), h4 = tf32rna(lo4[j]);
                *(float2*)&Ah_s[base + 2 * j] = make_float2(h0, h4);
                *(float2*)&Al_s[base + 2 * j] =
                    make_float2(tf32rna(lo0[j] - h0), tf32rna(lo4[j] - h4));
            }
            float4 wa = bpf[half * 2], wb = bpf[half * 2 + 1];
            float m0[4] = { wa.x, wa.y, wa.z, wa.w };
            float m4[4] = { wb.x, wb.y, wb.z, wb.w };
#pragma unroll
            for (int j = 0; j < 4; ++j) {
                const float h0 = tf32rna(m0[j]), h4 = tf32rna(m4[j]);
                *(float2*)&Bh_s[base + 2 * j] = make_float2(h0, h4);
                *(float2*)&Bl_s[base + 2 * j] =
                    make_float2(tf32rna(m0[j] - h0), tf32rna(m4[j] - h4));
            }
        }
        __syncthreads();

        // ---- prefetch next chunk while computing this one ----
        if (ch < 63) {
            const int k0n = (ch + 1) * 32;
#pragma unroll
            for (int i = 0; i < 4; ++i) {
                apf[i] = *(const float4*)(Ab + (size_t)gr * 2048 + k0n + gk + i * 4);
                bpf[i] = *(const float4*)(Bb + (size_t)gr * 2048 + k0n + gk + i * 4);
            }
        }

        // ---- compute: 4 k-steps of m16n8k8, 3 TF32 terms ----
#pragma unroll
        for (int ks = 0; ks < 4; ++ks) {
            uint32_t ahf[4][4], alf[4][4], bhf[4][2], blf[4][2];
#pragma unroll
            for (int mt = 0; mt < 4; ++mt) {
                const int r0 = warp_m + mt * 16 + g;
                const int off = ks * 8 + 2 * tig;
                uint2 p0 = *(const uint2*)&Ah_s[r0 * G_LDS + off];
                uint2 p1 = *(const uint2*)&Ah_s[(r0 + 8) * G_LDS + off];
                ahf[mt][0] = p0.x; ahf[mt][1] = p1.x;
                ahf[mt][2] = p0.y; ahf[mt][3] = p1.y;
                uint2 q0 = *(const uint2*)&Al_s[r0 * G_LDS + off];
                uint2 q1 = *(const uint2*)&Al_s[(r0 + 8) * G_LDS + off];
                alf[mt][0] = q0.x; alf[mt][1] = q1.x;
                alf[mt][2] = q0.y; alf[mt][3] = q1.y;
            }
#pragma unroll
            for (int nt = 0; nt < 4; ++nt) {
                const int n0 = warp_n + nt * 8 + g;
                const int off = ks * 8 + 2 * tig;
                uint2 p = *(const uint2*)&Bh_s[n0 * G_LDS + off];
                bhf[nt][0] = p.x; bhf[nt][1] = p.y;
                uint2 q = *(const uint2*)&Bl_s[n0 * G_LDS + off];
                blf[nt][0] = q.x; blf[nt][1] = q.y;
            }
#pragma unroll
            for (int mt = 0; mt < 4; ++mt)
#pragma unroll
                for (int nt = 0; nt < 4; ++nt) {
                    mma_tf32(c[mt][nt], ahf[mt], bhf[nt]);
                    mma_tf32(c[mt][nt], ahf[mt], blf[nt]);
                    mma_tf32(c[mt][nt], alf[mt], bhf[nt]);
                }
        }
        __syncthreads();
    }

    // ---- epilogue ----
#pragma unroll
    for (int mt = 0; mt < 4; ++mt) {
        const int row0 = bm * 128 + warp_m + mt * 16 + g;
#pragma unroll
        for (int nt = 0; nt < 4; ++nt) {
            const int coln = warp_n + nt * 8 + 2 * tig;   // within 128-wide tile
            if (mode == 3) {
                float* d0 = Cext + (size_t)row0 * 2048 + bn * 128 + coln;
                float* d1 = Cext + (size_t)(row0 + 8) * 2048 + bn * 128 + coln;
                d0[0] = nn_fix(c[mt][nt][0]); d0[1] = nn_fix(c[mt][nt][1]);
                d1[0] = nn_fix(c[mt][nt][2]); d1[1] = nn_fix(c[mt][nt][3]);
            } else {
                float* Cg = (mode == 0) ? g_q : (mode == 1) ? g_k : g_v;
                float* base = Cg + (size_t)bn * (TSEQ * HDIM);
                *(float2*)&base[(size_t)row0 * HDIM + coln] =
                    make_float2(c[mt][nt][0], c[mt][nt][1]);
                *(float2*)&base[(size_t)(row0 + 8) * HDIM + coln] =
                    make_float2(c[mt][nt][2], c[mt][nt][3]);
            }
        }
    }
}

// ---------------- RoPE in-place on g_q, g_k ----------------------------------
__global__ void rope_kernel()
{
    const int t = blockIdx.x;      // 0..2047
    const int i = threadIdx.x;     // 0..63 (pair index)
    const float pw = (float)pow(10000.0, (double)(2 * i) / 128.0);
    const float inv = 1.0f / pw;
    const float freq = (float)t * inv;
    const float c = cosf(freq);
    const float s = sinf(freq);
#pragma unroll 4
    for (int h = 0; h < NHEAD; ++h) {
        float* q = g_q + ((size_t)(h * TSEQ + t)) * HDIM;
        float x1 = q[i], x2 = q[i + 64];
        q[i]      = __fadd_rn(__fmul_rn(x1, c), __fmul_rn(-x2, s));
        q[i + 64] = __fadd_rn(__fmul_rn(x2, c), __fmul_rn(x1, s));
        float* k = g_k + ((size_t)(h * TSEQ + t)) * HDIM;
        float y1 = k[i], y2 = k[i + 64];
        k[i]      = __fadd_rn(__fmul_rn(y1, c), __fmul_rn(-y2, s));
        k[i + 64] = __fadd_rn(__fmul_rn(y2, c), __fmul_rn(y1, s));
    }
}

// ---------------- threefry-2x32, PARTITIONABLE path --------------------------
__device__ __forceinline__ unsigned rotl32(unsigned x, int d) {
    return (x << d) | (x >> (32 - d));
}

__device__ float jax_uniform42_partitionable(int h)
{
    const unsigned k0 = 0u, k1 = 42u;
    const unsigned k2 = k0 ^ k1 ^ 0x1BD11BDAu;
    const unsigned ks[3] = { k0, k1, k2 };
    unsigned x0 = 0u + k0;              // counter hi = 0
    unsigned x1 = (unsigned)h + k1;     // counter lo = h
    const int rotA[4] = { 13, 15, 26, 6 };
    const int rotB[4] = { 17, 29, 16, 24 };
#pragma unroll
    for (int i = 0; i < 5; ++i) {
        const int* R = (i & 1) ? rotB : rotA;
#pragma unroll
        for (int j = 0; j < 4; ++j) {
            x0 += x1;
            x1 = rotl32(x1, R[j]);
            x1 ^= x0;
        }
        x0 += ks[(i + 1) % 3];
        x1 += ks[(i + 2) % 3] + (unsigned)(i + 1);
    }
    const unsigned bits = x0 ^ x1;
    return __uint_as_float((bits >> 9) | 0x3f800000u) - 1.0f;
}

// ---------------- last-row stats: p, bern, v_e per head ----------------------
__global__ void __launch_bounds__(256) lastrow_kernel()
{
    const int h = blockIdx.x;
    const int tid = threadIdx.x;
    __shared__ float qv[128];
    __shared__ float s[2048];
    __shared__ float red[256];
    __shared__ float red2[256];
    __shared__ float sh_scale;

    if (tid < 128) qv[tid] = g_q[((size_t)h * TSEQ + 2047) * HDIM + tid];
    __syncthreads();

    for (int k = tid; k < 2048; k += 256) {
        const bool keep = (k < 204) || (k >= 1229);
        float val = -INFINITY;
        if (keep) {
            const float4* kr = (const float4*)(g_k + ((size_t)h * TSEQ + k) * HDIM);
            const float4* q4 = (const float4*)qv;
            float dot = 0.0f;
#pragma unroll
            for (int d4 = 0; d4 < 32; ++d4) {
                float4 a = q4[d4]; float4 b = kr[d4];
                dot = fmaf(a.x, b.x, dot); dot = fmaf(a.y, b.y, dot);
                dot = fmaf(a.z, b.z, dot); dot = fmaf(a.w, b.w, dot);
            }
            val = dot / 11.313708498984760f;  // / sqrt(128)
        }
        s[k] = val;
    }
    __syncthreads();

    float lm = -INFINITY;
    for (int k = tid; k < 2048; k += 256) lm = fmaxf(lm, s[k]);
    red[tid] = lm;
    __syncthreads();
    for (int st = 128; st > 0; st >>= 1) {
        if (tid < st) red[tid] = fmaxf(red[tid], red[tid + st]);
        __syncthreads();
    }
    const float m = red[0];
    __syncthreads();

    float ls = 0.0f, lrS = 0.0f;
    for (int k = tid; k < 2048; k += 256) {
        if ((k < 204) || (k >= 1229)) {
            const float e = expf(s[k] - m);
            ls += e;
            if (k >= 1230) lrS += e;
        }
    }
    red[tid] = ls; red2[tid] = lrS;
    __syncthreads();
    for (int st = 128; st > 0; st >>= 1) {
        if (tid < st) { red[tid] += red[tid + st]; red2[tid] += red2[tid + st]; }
        __syncthreads();
    }
    if (tid == 0) {
        const float L = red[0], R = red2[0];
        const float Pev = expf(s[1229] - m) / L;
        const float mean = (R / L) / 818.0f + 1e-6f;
        float p = Pev / mean;
        if (isnan(p)) p = 0.0f;
        p = fminf(fmaxf(p, 0.0f), 1.0f);
        const float u = jax_uniform42_partitionable(h);
        sh_scale = (u < p) ? 1.0f : 0.0f;
    }
    __syncthreads();
    if (tid < 128)
        g_ve[h * HDIM + tid] =
            (g_v[((size_t)h * TSEQ + 1229) * HDIM + tid] * sh_scale) / 819.0f;
}

// ---------------- flash-style attention over kept K columns ------------------
// (R5 scalar version — proven fastest FFMA formulation)
#define ATTN_SMEM_FLOATS (64*129 + 64*129 + 64*132 + 64*66 + 256)
#define ATTN_SMEM_BYTES  (ATTN_SMEM_FLOATS * 4)

__global__ void __launch_bounds__(256) attn_kernel()
{
    extern __shared__ float sm[];
    float* Qs   = sm;
    float* Ks   = Qs + 64 * 129;
    float* Vs   = Ks + 64 * 129;
    float* S    = Vs + 64 * 132;
    float* m_s  = S + 64 * 66;
    float* l_s  = m_s + 64;
    float* lr_s = l_s + 64;
    float* fac_s = lr_s + 64;

    const int h   = blockIdx.y;
    const int qt  = blockIdx.x;
    const int tid = threadIdx.x;
    const int ty  = tid >> 4;
    const int tx  = tid & 15;
    const int r0  = ty << 2;
    const int cS0 = tx << 2;
    const int cV0 = tx << 3;

    const int ldr = tid >> 5;
    const int ldc = (tid & 31) << 2;

    const float* qbase = g_q + ((size_t)h * TSEQ + qt * 64) * HDIM;
#pragma unroll
    for (int it = 0; it < 8; ++it) {
        const int j = ldr + it * 8;
        float4 v = *(const float4*)(qbase + (size_t)j * HDIM + ldc);
        Qs[j * 129 + ldc + 0] = v.x; Qs[j * 129 + ldc + 1] = v.y;
        Qs[j * 129 + ldc + 2] = v.z; Qs[j * 129 + ldc + 3] = v.w;
    }
    if (tid < 64) { m_s[tid] = -INFINITY; l_s[tid] = 0.0f; lr_s[tid] = 0.0f; }

    float acc[4][8];
#pragma unroll
    for (int i = 0; i < 4; ++i)
#pragma unroll
        for (int j = 0; j < 8; ++j) acc[i][j] = 0.0f;

    __syncthreads();

    for (int tile = 0; tile < 17; ++tile) {
        const int kb   = (tile < 4) ? tile * 64 : 1229 + (tile - 4) * 64;
        const int kend = (tile < 4) ? 204 : 2048;

#pragma unroll
        for (int it = 0; it < 8; ++it) {
            const int j = ldr + it * 8;
            const int kc = kb + j;
            float4 kv = make_float4(0.f, 0.f, 0.f, 0.f);
            float4 vv = kv;
            if (kc < kend) {
                kv = *(const float4*)(g_k + ((size_t)h * TSEQ + kc) * HDIM + ldc);
                vv = *(const float4*)(g_v + ((size_t)h * TSEQ + kc) * HDIM + ldc);
            }
            Ks[j * 129 + ldc + 0] = kv.x; Ks[j * 129 + ldc + 1] = kv.y;
            Ks[j * 129 + ldc + 2] = kv.z; Ks[j * 129 + ldc + 3] = kv.w;
            *(float4*)&Vs[j * 132 + ldc] = vv;
        }
        __syncthreads();

        float sacc[4][4];
#pragma unroll
        for (int i = 0; i < 4; ++i)
#pragma unroll
            for (int j = 0; j < 4; ++j) sacc[i][j] = 0.0f;

        const float* q0 = Qs + (r0 + 0) * 129;
        const float* q1 = Qs + (r0 + 1) * 129;
        const float* q2 = Qs + (r0 + 2) * 129;
        const float* q3 = Qs + (r0 + 3) * 129;
        const float* kp0 = Ks + (cS0 + 0) * 129;
        const float* kp1 = Ks + (cS0 + 1) * 129;
        const float* kp2 = Ks + (cS0 + 2) * 129;
        const float* kp3 = Ks + (cS0 + 3) * 129;
#pragma unroll 8
        for (int kk = 0; kk < 128; ++kk) {
            const float a0 = q0[kk], a1 = q1[kk], a2 = q2[kk], a3 = q3[kk];
            const float b0 = kp0[kk], b1 = kp1[kk], b2 = kp2[kk], b3 = kp3[kk];
            sacc[0][0] = fmaf(a0, b0, sacc[0][0]); sacc[0][1] = fmaf(a0, b1, sacc[0][1]);
            sacc[0][2] = fmaf(a0, b2, sacc[0][2]); sacc[0][3] = fmaf(a0, b3, sacc[0][3]);
            sacc[1][0] = fmaf(a1, b0, sacc[1][0]); sacc[1][1] = fmaf(a1, b1, sacc[1][1]);
            sacc[1][2] = fmaf(a1, b2, sacc[1][2]); sacc[1][3] = fmaf(a1, b3, sacc[1][3]);
            sacc[2][0] = fmaf(a2, b0, sacc[2][0]); sacc[2][1] = fmaf(a2, b1, sacc[2][1]);
            sacc[2][2] = fmaf(a2, b2, sacc[2][2]); sacc[2][3] = fmaf(a2, b3, sacc[2][3]);
            sacc[3][0] = fmaf(a3, b0, sacc[3][0]); sacc[3][1] = fmaf(a3, b1, sacc[3][1]);
            sacc[3][2] = fmaf(a3, b2, sacc[3][2]); sacc[3][3] = fmaf(a3, b3, sacc[3][3]);
        }
#pragma unroll
        for (int i = 0; i < 4; ++i)
#pragma unroll
            for (int j = 0; j < 4; ++j) {
                const int kc = kb + cS0 + j;
                S[(r0 + i) * 66 + cS0 + j] =
                    (kc < kend) ? sacc[i][j] / 11.313708498984760f : -1e30f;
            }
        __syncthreads();

        if (tid < 64) {
            const int r = tid;
            float* Sr = S + r * 66;
            float tm = -1e30f;
#pragma unroll 8
            for (int j = 0; j < 64; ++j) tm = fmaxf(tm, Sr[j]);
            const float mo = m_s[r];
            const float mn = fmaxf(mo, tm);
            const float fac = expf(mo - mn);
            float sum = 0.0f, sumr = 0.0f;
#pragma unroll 4
            for (int j = 0; j < 64; ++j) {
                const float e = expf(Sr[j] - mn);
                Sr[j] = e;
                sum += e;
                if (kb + j >= 1230) sumr += e;
            }
            l_s[r]  = l_s[r]  * fac + sum;
            lr_s[r] = lr_s[r] * fac + sumr;
            m_s[r]  = mn;
            fac_s[r] = fac;
        }
        __syncthreads();

        {
            const float f0 = fac_s[r0 + 0], f1 = fac_s[r0 + 1];
            const float f2 = fac_s[r0 + 2], f3 = fac_s[r0 + 3];
#pragma unroll
            for (int j = 0; j < 8; ++j) {
                acc[0][j] *= f0; acc[1][j] *= f1; acc[2][j] *= f2; acc[3][j] *= f3;
            }
        }
#pragma unroll 2
        for (int jp = 0; jp < 64; ++jp) {
            const float p0 = S[(r0 + 0) * 66 + jp];
            const float p1 = S[(r0 + 1) * 66 + jp];
            const float p2 = S[(r0 + 2) * 66 + jp];
            const float p3 = S[(r0 + 3) * 66 + jp];
            float vv[8];
            *(float4*)&vv[0] = *(const float4*)&Vs[jp * 132 + cV0];
            *(float4*)&vv[4] = *(const float4*)&Vs[jp * 132 + cV0 + 4];
#pragma unroll
            for (int j = 0; j < 8; ++j) {
                acc[0][j] = fmaf(p0, vv[j], acc[0][j]);
                acc[1][j] = fmaf(p1, vv[j], acc[1][j]);
                acc[2][j] = fmaf(p2, vv[j], acc[2][j]);
                acc[3][j] = fmaf(p3, vv[j], acc[3][j]);
            }
        }
        __syncthreads();
    }

    const int qg0 = qt * 64;
#pragma unroll
    for (int i = 0; i < 4; ++i) {
        const int r = r0 + i;
        const int qrow = qg0 + r;
        const float linv = 1.0f / l_s[r];
        const float corr = (qrow >= 1792) ? lr_s[r] * linv : 0.0f;
#pragma unroll
        for (int j = 0; j < 8; ++j) {
            const int dcol = cV0 + j;
            const float o = acc[i][j] * linv + corr * g_ve[h * HDIM + dcol];
            g_ctx[(size_t)qrow * 2048 + h * HDIM + dcol] = o;
        }
    }
}

// ---------------- launch ------------------------------------------------------
extern "C" void kernel_launch(void* const* d_in, const int* in_sizes, int n_in,
                              void* d_out, int out_size)
{
    (void)in_sizes; (void)n_in; (void)out_size;
    const float* hs = (const float*)d_in[0];
    const float* Wq = (const float*)d_in[1];
    const float* Wk = (const float*)d_in[2];
    const float* Wv = (const float*)d_in[3];
    const float* Wo = (const float*)d_in[4];
    float* out = (float*)d_out;

    cudaFuncSetAttribute(gemm_tc_kernel,
                         cudaFuncAttributeMaxDynamicSharedMemorySize,
                         G_SMEM_BYTES);
    cudaFuncSetAttribute(attn_kernel,
                         cudaFuncAttributeMaxDynamicSharedMemorySize,
                         ATTN_SMEM_BYTES);

    dim3 ggrid(16, 16);
    gemm_tc_kernel<<<ggrid, 256, G_SMEM_BYTES>>>(hs, Wq, nullptr, 0);
    gemm_tc_kernel<<<ggrid, 256, G_SMEM_BYTES>>>(hs, Wk, nullptr, 1);
    gemm_tc_kernel<<<ggrid, 256, G_SMEM_BYTES>>>(hs, Wv, nullptr, 2);
    rope_kernel<<<2048, 64>>>();
    lastrow_kernel<<<16, 256>>>();
    attn_kernel<<<dim3(32, 16), 256, ATTN_SMEM_BYTES>>>();
    gemm_tc_kernel<<<ggrid, 256, G_SMEM_BYTES>>>(nullptr, Wo, out, 3);
}

// round 9
// speedup vs baseline: 1.3719x; 1.3719x over previous
#include <cuda_runtime.h>
#include <math.h>
#include <stdint.h>

// Problem constants
#define TSEQ 2048
#define NHEAD 16
#define HDIM 128
// mask: keep k < 204 or k >= 1229 ; evict = 1229 ; recent rb = 819
// last_start = 1792 ; mean over k in [1230, 2048) -> 818 elements

// ---------------- scratch (static device globals; no allocation) -------------
__device__ float g_q[NHEAD * TSEQ * HDIM];   // [h][t][d], rope applied
__device__ float g_k[NHEAD * TSEQ * HDIM];
__device__ float g_v[NHEAD * TSEQ * HDIM];
__device__ float g_ctx[TSEQ * 2048];         // [t][h*128+d]
__device__ float g_ve[NHEAD * HDIM];         // v_e per head (includes bern/rb)

// nan_to_num(nan=0, posinf=1e4, neginf=-1e4): replaces non-finite ONLY
__device__ __forceinline__ float nn_fix(float x) {
    if (isnan(x)) return 0.0f;
    if (isinf(x)) return x > 0.0f ? 10000.0f : -10000.0f;
    return x;
}

__device__ __forceinline__ float tf32rna(float x) {
    float r;
    asm("cvt.rna.tf32.f32 %0, %1;" : "=f"(r) : "f"(x));
    return r;
}

// portable (non-'a') tensor core: mma.sync m16n8k8 tf32, fp32 accumulate
__device__ __forceinline__ void mma_tf32(float* d, const uint32_t* a,
                                         const uint32_t* b) {
    asm volatile(
        "mma.sync.aligned.m16n8k8.row.col.f32.tf32.tf32.f32 "
        "{%0,%1,%2,%3}, {%4,%5,%6,%7}, {%8,%9}, {%0,%1,%2,%3};"
        : "+f"(d[0]), "+f"(d[1]), "+f"(d[2]), "+f"(d[3])
        : "r"(a[0]), "r"(a[1]), "r"(a[2]), "r"(a[3]), "r"(b[0]), "r"(b[1]));
}

// ============ mma.sync TF32x3 GEMM: C[M,N] = A[M,K] * B[N,K]^T ===============
// M=N=K=2048, CTA tile 128x128, 256 threads (8 warps, 2x4), warp tile 64x32.
// SMEM chunk: 32 K-columns, PLAIN row layout, row stride 36 floats.
// Fragment loads are LDS.32: bank = (4g + tig) mod 32 -> conflict-free.
#define G_LDS 36
#define G_TILE_FLOATS (128 * G_LDS)
#define G_SMEM_FLOATS (4 * G_TILE_FLOATS)   // Ah, Al, Bh, Bl
#define G_SMEM_BYTES  (G_SMEM_FLOATS * 4)

__global__ void __launch_bounds__(256, 1)
gemm_tc_kernel(const float* __restrict__ Aext, const float* __restrict__ B,
               float* __restrict__ Cext, int mode)
{
    extern __shared__ float gsm[];
    float* Ah_s = gsm;
    float* Al_s = Ah_s + G_TILE_FLOATS;
    float* Bh_s = Al_s + G_TILE_FLOATS;
    float* Bl_s = Bh_s + G_TILE_FLOATS;

    const float* A = (mode == 3) ? (const float*)g_ctx : Aext;
    const bool fixA = (mode != 3);

    const int tid  = threadIdx.x;
    const int wid  = tid >> 5;
    const int lane = tid & 31;
    const int g    = lane >> 2;     // group 0..7 (fragment row)
    const int tig  = lane & 3;      // thread in group 0..3 (fragment col)
    const int bm = blockIdx.y, bn = blockIdx.x;

    const int warp_m = (wid >> 2) * 64;   // 0 or 64
    const int warp_n = (wid & 3) * 32;    // 0,32,64,96

    // C fragments: 4 m-tiles x 4 n-tiles x 4 regs
    float c[4][4][4];
#pragma unroll
    for (int i = 0; i < 4; ++i)
#pragma unroll
        for (int j = 0; j < 4; ++j)
#pragma unroll
            for (int q = 0; q < 4; ++q) c[i][j][q] = 0.0f;

    const float* Ab = A + (size_t)(bm * 128) * 2048;
    const float* Bb = B + (size_t)(bn * 128) * 2048;

    // GMEM load assignment: row = tid>>1, k half = (tid&1)*16
    const int gr = tid >> 1;
    const int gk = (tid & 1) * 16;

    float4 apf[4], bpf[4];
    // prefetch chunk 0
#pragma unroll
    for (int i = 0; i < 4; ++i) {
        apf[i] = *(const float4*)(Ab + (size_t)gr * 2048 + gk + i * 4);
        bpf[i] = *(const float4*)(Bb + (size_t)gr * 2048 + gk + i * 4);
    }

    for (int ch = 0; ch < 64; ++ch) {
        // ---- split prefetched chunk into hi/lo, store plain layout ----
        const int sbase = gr * G_LDS + gk;
#pragma unroll
        for (int i = 0; i < 4; ++i) {
            float4 va = apf[i];
            if (fixA) {
                va.x = nn_fix(va.x); va.y = nn_fix(va.y);
                va.z = nn_fix(va.z); va.w = nn_fix(va.w);
            }
            float4 ah = make_float4(tf32rna(va.x), tf32rna(va.y),
                                    tf32rna(va.z), tf32rna(va.w));
            float4 al = make_float4(tf32rna(va.x - ah.x), tf32rna(va.y - ah.y),
                                    tf32rna(va.z - ah.z), tf32rna(va.w - ah.w));
            *(float4*)&Ah_s[sbase + 4 * i] = ah;
            *(float4*)&Al_s[sbase + 4 * i] = al;

            float4 vb = bpf[i];
            float4 bh = make_float4(tf32rna(vb.x), tf32rna(vb.y),
                                    tf32rna(vb.z), tf32rna(vb.w));
            float4 bl = make_float4(tf32rna(vb.x - bh.x), tf32rna(vb.y - bh.y),
                                    tf32rna(vb.z - bh.z), tf32rna(vb.w - bh.w));
            *(float4*)&Bh_s[sbase + 4 * i] = bh;
            *(float4*)&Bl_s[sbase + 4 * i] = bl;
        }
        __syncthreads();

        // ---- prefetch next chunk while computing this one ----
        if (ch < 63) {
            const int k0n = (ch + 1) * 32;
#pragma unroll
            for (int i = 0; i < 4; ++i) {
                apf[i] = *(const float4*)(Ab + (size_t)gr * 2048 + k0n + gk + i * 4);
                bpf[i] = *(const float4*)(Bb + (size_t)gr * 2048 + k0n + gk + i * 4);
            }
        }

        // ---- compute: 4 k-steps of m16n8k8, 3 TF32 terms ----
#pragma unroll
        for (int ks = 0; ks < 4; ++ks) {
            const int off = ks * 8 + tig;
            uint32_t ahf[4][4], alf[4][4], bhf[4][2], blf[4][2];
#pragma unroll
            for (int mt = 0; mt < 4; ++mt) {
                const int r0 = (warp_m + mt * 16 + g) * G_LDS + off;
                ahf[mt][0] = __float_as_uint(Ah_s[r0]);
                ahf[mt][1] = __float_as_uint(Ah_s[r0 + 8 * G_LDS]);
                ahf[mt][2] = __float_as_uint(Ah_s[r0 + 4]);
                ahf[mt][3] = __float_as_uint(Ah_s[r0 + 8 * G_LDS + 4]);
                alf[mt][0] = __float_as_uint(Al_s[r0]);
                alf[mt][1] = __float_as_uint(Al_s[r0 + 8 * G_LDS]);
                alf[mt][2] = __float_as_uint(Al_s[r0 + 4]);
                alf[mt][3] = __float_as_uint(Al_s[r0 + 8 * G_LDS + 4]);
            }
#pragma unroll
            for (int nt = 0; nt < 4; ++nt) {
                const int n0 = (warp_n + nt * 8 + g) * G_LDS + off;
                bhf[nt][0] = __float_as_uint(Bh_s[n0]);
                bhf[nt][1] = __float_as_uint(Bh_s[n0 + 4]);
                blf[nt][0] = __float_as_uint(Bl_s[n0]);
                blf[nt][1] = __float_as_uint(Bl_s[n0 + 4]);
            }
#pragma unroll
            for (int mt = 0; mt < 4; ++mt)
#pragma unroll
                for (int nt = 0; nt < 4; ++nt) {
                    mma_tf32(c[mt][nt], ahf[mt], bhf[nt]);
                    mma_tf32(c[mt][nt], ahf[mt], blf[nt]);
                    mma_tf32(c[mt][nt], alf[mt], bhf[nt]);
                }
        }
        __syncthreads();
    }

    // ---- epilogue ----
#pragma unroll
    for (int mt = 0; mt < 4; ++mt) {
        const int row0 = bm * 128 + warp_m + mt * 16 + g;
#pragma unroll
        for (int nt = 0; nt < 4; ++nt) {
            const int coln = warp_n + nt * 8 + 2 * tig;   // within 128-wide tile
            if (mode == 3) {
                float* d0 = Cext + (size_t)row0 * 2048 + bn * 128 + coln;
                float* d1 = Cext + (size_t)(row0 + 8) * 2048 + bn * 128 + coln;
                d0[0] = nn_fix(c[mt][nt][0]); d0[1] = nn_fix(c[mt][nt][1]);
                d1[0] = nn_fix(c[mt][nt][2]); d1[1] = nn_fix(c[mt][nt][3]);
            } else {
                float* Cg = (mode == 0) ? g_q : (mode == 1) ? g_k : g_v;
                float* base = Cg + (size_t)bn * (TSEQ * HDIM);
                *(float2*)&base[(size_t)row0 * HDIM + coln] =
                    make_float2(c[mt][nt][0], c[mt][nt][1]);
                *(float2*)&base[(size_t)(row0 + 8) * HDIM + coln] =
                    make_float2(c[mt][nt][2], c[mt][nt][3]);
            }
        }
    }
}

// ---------------- RoPE in-place on g_q, g_k ----------------------------------
__global__ void rope_kernel()
{
    const int t = blockIdx.x;      // 0..2047
    const int i = threadIdx.x;     // 0..63 (pair index)
    const float pw = (float)pow(10000.0, (double)(2 * i) / 128.0);
    const float inv = 1.0f / pw;
    const float freq = (float)t * inv;
    const float c = cosf(freq);
    const float s = sinf(freq);
#pragma unroll 4
    for (int h = 0; h < NHEAD; ++h) {
        float* q = g_q + ((size_t)(h * TSEQ + t)) * HDIM;
        float x1 = q[i], x2 = q[i + 64];
        q[i]      = __fadd_rn(__fmul_rn(x1, c), __fmul_rn(-x2, s));
        q[i + 64] = __fadd_rn(__fmul_rn(x2, c), __fmul_rn(x1, s));
        float* k = g_k + ((size_t)(h * TSEQ + t)) * HDIM;
        float y1 = k[i], y2 = k[i + 64];
        k[i]      = __fadd_rn(__fmul_rn(y1, c), __fmul_rn(-y2, s));
        k[i + 64] = __fadd_rn(__fmul_rn(y2, c), __fmul_rn(y1, s));
    }
}

// ---------------- threefry-2x32, PARTITIONABLE path --------------------------
__device__ __forceinline__ unsigned rotl32(unsigned x, int d) {
    return (x << d) | (x >> (32 - d));
}

__device__ float jax_uniform42_partitionable(int h)
{
    const unsigned k0 = 0u, k1 = 42u;
    const unsigned k2 = k0 ^ k1 ^ 0x1BD11BDAu;
    const unsigned ks[3] = { k0, k1, k2 };
    unsigned x0 = 0u + k0;              // counter hi = 0
    unsigned x1 = (unsigned)h + k1;     // counter lo = h
    const int rotA[4] = { 13, 15, 26, 6 };
    const int rotB[4] = { 17, 29, 16, 24 };
#pragma unroll
    for (int i = 0; i < 5; ++i) {
        const int* R = (i & 1) ? rotB : rotA;
#pragma unroll
        for (int j = 0; j < 4; ++j) {
            x0 += x1;
            x1 = rotl32(x1, R[j]);
            x1 ^= x0;
        }
        x0 += ks[(i + 1) % 3];
        x1 += ks[(i + 2) % 3] + (unsigned)(i + 1);
    }
    const unsigned bits = x0 ^ x1;
    return __uint_as_float((bits >> 9) | 0x3f800000u) - 1.0f;
}

// ---------------- last-row stats: p, bern, v_e per head ----------------------
__global__ void __launch_bounds__(256) lastrow_kernel()
{
    const int h = blockIdx.x;
    const int tid = threadIdx.x;
    __shared__ float qv[128];
    __shared__ float s[2048];
    __shared__ float red[256];
    __shared__ float red2[256];
    __shared__ float sh_scale;

    if (tid < 128) qv[tid] = g_q[((size_t)h * TSEQ + 2047) * HDIM + tid];
    __syncthreads();

    for (int k = tid; k < 2048; k += 256) {
        const bool keep = (k < 204) || (k >= 1229);
        float val = -INFINITY;
        if (keep) {
            const float4* kr = (const float4*)(g_k + ((size_t)h * TSEQ + k) * HDIM);
            const float4* q4 = (const float4*)qv;
            float dot = 0.0f;
#pragma unroll
            for (int d4 = 0; d4 < 32; ++d4) {
                float4 a = q4[d4]; float4 b = kr[d4];
                dot = fmaf(a.x, b.x, dot); dot = fmaf(a.y, b.y, dot);
                dot = fmaf(a.z, b.z, dot); dot = fmaf(a.w, b.w, dot);
            }
            val = dot / 11.313708498984760f;  // / sqrt(128)
        }
        s[k] = val;
    }
    __syncthreads();

    float lm = -INFINITY;
    for (int k = tid; k < 2048; k += 256) lm = fmaxf(lm, s[k]);
    red[tid] = lm;
    __syncthreads();
    for (int st = 128; st > 0; st >>= 1) {
        if (tid < st) red[tid] = fmaxf(red[tid], red[tid + st]);
        __syncthreads();
    }
    const float m = red[0];
    __syncthreads();

    float ls = 0.0f, lrS = 0.0f;
    for (int k = tid; k < 2048; k += 256) {
        if ((k < 204) || (k >= 1229)) {
            const float e = expf(s[k] - m);
            ls += e;
            if (k >= 1230) lrS += e;
        }
    }
    red[tid] = ls; red2[tid] = lrS;
    __syncthreads();
    for (int st = 128; st > 0; st >>= 1) {
        if (tid < st) { red[tid] += red[tid + st]; red2[tid] += red2[tid + st]; }
        __syncthreads();
    }
    if (tid == 0) {
        const float L = red[0], R = red2[0];
        const float Pev = expf(s[1229] - m) / L;
        const float mean = (R / L) / 818.0f + 1e-6f;
        float p = Pev / mean;
        if (isnan(p)) p = 0.0f;
        p = fminf(fmaxf(p, 0.0f), 1.0f);
        const float u = jax_uniform42_partitionable(h);
        sh_scale = (u < p) ? 1.0f : 0.0f;
    }
    __syncthreads();
    if (tid < 128)
        g_ve[h * HDIM + tid] =
            (g_v[((size_t)h * TSEQ + 1229) * HDIM + tid] * sh_scale) / 819.0f;
}

// ---------------- flash-style attention over kept K columns ------------------
// (R5 scalar version — proven fastest FFMA formulation)
#define ATTN_SMEM_FLOATS (64*129 + 64*129 + 64*132 + 64*66 + 256)
#define ATTN_SMEM_BYTES  (ATTN_SMEM_FLOATS * 4)

__global__ void __launch_bounds__(256) attn_kernel()
{
    extern __shared__ float sm[];
    float* Qs   = sm;
    float* Ks   = Qs + 64 * 129;
    float* Vs   = Ks + 64 * 129;
    float* S    = Vs + 64 * 132;
    float* m_s  = S + 64 * 66;
    float* l_s  = m_s + 64;
    float* lr_s = l_s + 64;
    float* fac_s = lr_s + 64;

    const int h   = blockIdx.y;
    const int qt  = blockIdx.x;
    const int tid = threadIdx.x;
    const int ty  = tid >> 4;
    const int tx  = tid & 15;
    const int r0  = ty << 2;
    const int cS0 = tx << 2;
    const int cV0 = tx << 3;

    const int ldr = tid >> 5;
    const int ldc = (tid & 31) << 2;

    const float* qbase = g_q + ((size_t)h * TSEQ + qt * 64) * HDIM;
#pragma unroll
    for (int it = 0; it < 8; ++it) {
        const int j = ldr + it * 8;
        float4 v = *(const float4*)(qbase + (size_t)j * HDIM + ldc);
        Qs[j * 129 + ldc + 0] = v.x; Qs[j * 129 + ldc + 1] = v.y;
        Qs[j * 129 + ldc + 2] = v.z; Qs[j * 129 + ldc + 3] = v.w;
    }
    if (tid < 64) { m_s[tid] = -INFINITY; l_s[tid] = 0.0f; lr_s[tid] = 0.0f; }

    float acc[4][8];
#pragma unroll
    for (int i = 0; i < 4; ++i)
#pragma unroll
        for (int j = 0; j < 8; ++j) acc[i][j] = 0.0f;

    __syncthreads();

    for (int tile = 0; tile < 17; ++tile) {
        const int kb   = (tile < 4) ? tile * 64 : 1229 + (tile - 4) * 64;
        const int kend = (tile < 4) ? 204 : 2048;

#pragma unroll
        for (int it = 0; it < 8; ++it) {
            const int j = ldr + it * 8;
            const int kc = kb + j;
            float4 kv = make_float4(0.f, 0.f, 0.f, 0.f);
            float4 vv = kv;
            if (kc < kend) {
                kv = *(const float4*)(g_k + ((size_t)h * TSEQ + kc) * HDIM + ldc);
                vv = *(const float4*)(g_v + ((size_t)h * TSEQ + kc) * HDIM + ldc);
            }
            Ks[j * 129 + ldc + 0] = kv.x; Ks[j * 129 + ldc + 1] = kv.y;
            Ks[j * 129 + ldc + 2] = kv.z; Ks[j * 129 + ldc + 3] = kv.w;
            *(float4*)&Vs[j * 132 + ldc] = vv;
        }
        __syncthreads();

        float sacc[4][4];
#pragma unroll
        for (int i = 0; i < 4; ++i)
#pragma unroll
            for (int j = 0; j < 4; ++j) sacc[i][j] = 0.0f;

        const float* q0 = Qs + (r0 + 0) * 129;
        const float* q1 = Qs + (r0 + 1) * 129;
        const float* q2 = Qs + (r0 + 2) * 129;
        const float* q3 = Qs + (r0 + 3) * 129;
        const float* kp0 = Ks + (cS0 + 0) * 129;
        const float* kp1 = Ks + (cS0 + 1) * 129;
        const float* kp2 = Ks + (cS0 + 2) * 129;
        const float* kp3 = Ks + (cS0 + 3) * 129;
#pragma unroll 8
        for (int kk = 0; kk < 128; ++kk) {
            const float a0 = q0[kk], a1 = q1[kk], a2 = q2[kk], a3 = q3[kk];
            const float b0 = kp0[kk], b1 = kp1[kk], b2 = kp2[kk], b3 = kp3[kk];
            sacc[0][0] = fmaf(a0, b0, sacc[0][0]); sacc[0][1] = fmaf(a0, b1, sacc[0][1]);
            sacc[0][2] = fmaf(a0, b2, sacc[0][2]); sacc[0][3] = fmaf(a0, b3, sacc[0][3]);
            sacc[1][0] = fmaf(a1, b0, sacc[1][0]); sacc[1][1] = fmaf(a1, b1, sacc[1][1]);
            sacc[1][2] = fmaf(a1, b2, sacc[1][2]); sacc[1][3] = fmaf(a1, b3, sacc[1][3]);
            sacc[2][0] = fmaf(a2, b0, sacc[2][0]); sacc[2][1] = fmaf(a2, b1, sacc[2][1]);
            sacc[2][2] = fmaf(a2, b2, sacc[2][2]); sacc[2][3] = fmaf(a2, b3, sacc[2][3]);
            sacc[3][0] = fmaf(a3, b0, sacc[3][0]); sacc[3][1] = fmaf(a3, b1, sacc[3][1]);
            sacc[3][2] = fmaf(a3, b2, sacc[3][2]); sacc[3][3] = fmaf(a3, b3, sacc[3][3]);
        }
#pragma unroll
        for (int i = 0; i < 4; ++i)
#pragma unroll
            for (int j = 0; j < 4; ++j) {
                const int kc = kb + cS0 + j;
                S[(r0 + i) * 66 + cS0 + j] =
                    (kc < kend) ? sacc[i][j] / 11.313708498984760f : -1e30f;
            }
        __syncthreads();

        if (tid < 64) {
            const int r = tid;
            float* Sr = S + r * 66;
            float tm = -1e30f;
#pragma unroll 8
            for (int j = 0; j < 64; ++j) tm = fmaxf(tm, Sr[j]);
            const float mo = m_s[r];
            const float mn = fmaxf(mo, tm);
            const float fac = expf(mo - mn);
            float sum = 0.0f, sumr = 0.0f;
#pragma unroll 4
            for (int j = 0; j < 64; ++j) {
                const float e = expf(Sr[j] - mn);
                Sr[j] = e;
                sum += e;
                if (kb + j >= 1230) sumr += e;
            }
            l_s[r]  = l_s[r]  * fac + sum;
            lr_s[r] = lr_s[r] * fac + sumr;
            m_s[r]  = mn;
            fac_s[r] = fac;
        }
        __syncthreads();

        {
            const float f0 = fac_s[r0 + 0], f1 = fac_s[r0 + 1];
            const float f2 = fac_s[r0 + 2], f3 = fac_s[r0 + 3];
#pragma unroll
            for (int j = 0; j < 8; ++j) {
                acc[0][j] *= f0; acc[1][j] *= f1; acc[2][j] *= f2; acc[3][j] *= f3;
            }
        }
#pragma unroll 2
        for (int jp = 0; jp < 64; ++jp) {
            const float p0 = S[(r0 + 0) * 66 + jp];
            const float p1 = S[(r0 + 1) * 66 + jp];
            const float p2 = S[(r0 + 2) * 66 + jp];
            const float p3 = S[(r0 + 3) * 66 + jp];
            float vv[8];
            *(float4*)&vv[0] = *(const float4*)&Vs[jp * 132 + cV0];
            *(float4*)&vv[4] = *(const float4*)&Vs[jp * 132 + cV0 + 4];
#pragma unroll
            for (int j = 0; j < 8; ++j) {
                acc[0][j] = fmaf(p0, vv[j], acc[0][j]);
                acc[1][j] = fmaf(p1, vv[j], acc[1][j]);
                acc[2][j] = fmaf(p2, vv[j], acc[2][j]);
                acc[3][j] = fmaf(p3, vv[j], acc[3][j]);
            }
        }
        __syncthreads();
    }

    const int qg0 = qt * 64;
#pragma unroll
    for (int i = 0; i < 4; ++i) {
        const int r = r0 + i;
        const int qrow = qg0 + r;
        const float linv = 1.0f / l_s[r];
        const float corr = (qrow >= 1792) ? lr_s[r] * linv : 0.0f;
#pragma unroll
        for (int j = 0; j < 8; ++j) {
            const int dcol = cV0 + j;
            const float o = acc[i][j] * linv + corr * g_ve[h * HDIM + dcol];
            g_ctx[(size_t)qrow * 2048 + h * HDIM + dcol] = o;
        }
    }
}

// ---------------- launch ------------------------------------------------------
extern "C" void kernel_launch(void* const* d_in, const int* in_sizes, int n_in,
                              void* d_out, int out_size)
{
    (void)in_sizes; (void)n_in; (void)out_size;
    const float* hs = (const float*)d_in[0];
    const float* Wq = (const float*)d_in[1];
    const float* Wk = (const float*)d_in[2];
    const float* Wv = (const float*)d_in[3];
    const float* Wo = (const float*)d_in[4];
    float* out = (float*)d_out;

    cudaFuncSetAttribute(gemm_tc_kernel,
                         cudaFuncAttributeMaxDynamicSharedMemorySize,
                         G_SMEM_BYTES);
    cudaFuncSetAttribute(attn_kernel,
                         cudaFuncAttributeMaxDynamicSharedMemorySize,
                         ATTN_SMEM_BYTES);

    dim3 ggrid(16, 16);
    gemm_tc_kernel<<<ggrid, 256, G_SMEM_BYTES>>>(hs, Wq, nullptr, 0);
    gemm_tc_kernel<<<ggrid, 256, G_SMEM_BYTES>>>(hs, Wk, nullptr, 1);
    gemm_tc_kernel<<<ggrid, 256, G_SMEM_BYTES>>>(hs, Wv, nullptr, 2);
    rope_kernel<<<2048, 64>>>();
    lastrow_kernel<<<16, 256>>>();
    attn_kernel<<<dim3(32, 16), 256, ATTN_SMEM_BYTES>>>();
    gemm_tc_kernel<<<ggrid, 256, G_SMEM_BYTES>>>(nullptr, Wo, out, 3);
}

// round 10
// speedup vs baseline: 1.4030x; 1.0226x over previous
#include <cuda_runtime.h>
#include <math.h>
#include <stdint.h>

// Problem constants
#define TSEQ 2048
#define NHEAD 16
#define HDIM 128
// mask: keep k < 204 or k >= 1229 ; evict = 1229 ; recent rb = 819
// last_start = 1792 ; mean over k in [1230, 2048) -> 818 elements

// ---------------- scratch (static device globals; no allocation) -------------
__device__ float g_q[NHEAD * TSEQ * HDIM];   // [h][t][d], rope applied
__device__ float g_k[NHEAD * TSEQ * HDIM];
__device__ float g_v[NHEAD * TSEQ * HDIM];
__device__ float g_ctx[TSEQ * 2048];         // [t][h*128+d]
__device__ float g_ve[NHEAD * HDIM];         // v_e per head (includes bern/rb)

// nan_to_num(nan=0, posinf=1e4, neginf=-1e4): replaces non-finite ONLY
__device__ __forceinline__ float nn_fix(float x) {
    if (isnan(x)) return 0.0f;
    if (isinf(x)) return x > 0.0f ? 10000.0f : -10000.0f;
    return x;
}

__device__ __forceinline__ float tf32rna(float x) {
    float r;
    asm("cvt.rna.tf32.f32 %0, %1;" : "=f"(r) : "f"(x));
    return r;
}

// portable (non-'a') tensor core: mma.sync m16n8k8 tf32, fp32 accumulate
__device__ __forceinline__ void mma_tf32(float* d, const uint32_t* a,
                                         const uint32_t* b) {
    asm volatile(
        "mma.sync.aligned.m16n8k8.row.col.f32.tf32.tf32.f32 "
        "{%0,%1,%2,%3}, {%4,%5,%6,%7}, {%8,%9}, {%0,%1,%2,%3};"
        : "+f"(d[0]), "+f"(d[1]), "+f"(d[2]), "+f"(d[3])
        : "r"(a[0]), "r"(a[1]), "r"(a[2]), "r"(a[3]), "r"(b[0]), "r"(b[1]));
}

// ============ mma.sync TF32x3 GEMM: C[M,N] = A[M,K] * B[N,K]^T ===============
// M=N=K=2048, CTA tile 128x128, 256 threads (8 warps, 2x4), warp tile 64x32.
// SMEM holds fp32 tiles (hi/lo split done in REGISTERS after fragment load).
// Double-buffered stages; ONE __syncthreads per chunk.
// Row stride 36 -> fragment LDS.32 bank = (4g + tig) mod 32, conflict-free.
#define G_LDS 36
#define G_TILE_FLOATS (128 * G_LDS)
#define G_SMEM_FLOATS (4 * G_TILE_FLOATS)   // 2 stages x (A, B)
#define G_SMEM_BYTES  (G_SMEM_FLOATS * 4)

__global__ void __launch_bounds__(256, 1)
gemm_tc_kernel(const float* __restrict__ Aext, const float* __restrict__ B,
               float* __restrict__ Cext, int mode)
{
    extern __shared__ float gsm[];
    // stage s: A at gsm + s*2*TILE, B at gsm + s*2*TILE + TILE
    const float* Aglob = (mode == 3) ? (const float*)g_ctx : Aext;
    const bool fixA = (mode != 3);

    const int tid  = threadIdx.x;
    const int wid  = tid >> 5;
    const int lane = tid & 31;
    const int g    = lane >> 2;     // fragment row 0..7
    const int tig  = lane & 3;      // fragment col 0..3
    const int bm = blockIdx.y, bn = blockIdx.x;

    const int warp_m = (wid >> 2) * 64;   // 0 or 64
    const int warp_n = (wid & 3) * 32;    // 0,32,64,96

    float c[4][4][4];
#pragma unroll
    for (int i = 0; i < 4; ++i)
#pragma unroll
        for (int j = 0; j < 4; ++j)
#pragma unroll
            for (int q = 0; q < 4; ++q) c[i][j][q] = 0.0f;

    const float* Ab = Aglob + (size_t)(bm * 128) * 2048;
    const float* Bb = B + (size_t)(bn * 128) * 2048;

    // GMEM load assignment: row = tid>>1, k-half = (tid&1)*16
    const int gr = tid >> 1;
    const int gk = (tid & 1) * 16;
    const int sbase = gr * G_LDS + gk;

    float4 apf[4], bpf[4];
    // ---- chunk 0: prefetch + store to stage 0 ----
#pragma unroll
    for (int i = 0; i < 4; ++i) {
        apf[i] = *(const float4*)(Ab + (size_t)gr * 2048 + gk + i * 4);
        bpf[i] = *(const float4*)(Bb + (size_t)gr * 2048 + gk + i * 4);
    }
#pragma unroll
    for (int i = 0; i < 4; ++i) {
        float4 va = apf[i];
        if (fixA) {
            va.x = nn_fix(va.x); va.y = nn_fix(va.y);
            va.z = nn_fix(va.z); va.w = nn_fix(va.w);
        }
        *(float4*)&gsm[sbase + 4 * i] = va;
        *(float4*)&gsm[G_TILE_FLOATS + sbase + 4 * i] = bpf[i];
    }

    for (int ch = 0; ch < 64; ++ch) {
        const int s = ch & 1;
        float* As = gsm + (size_t)s * (2 * G_TILE_FLOATS);
        float* Bs = As + G_TILE_FLOATS;
        __syncthreads();    // stage s stores visible; stage s^1 fully consumed

        // prefetch next chunk (overlaps compute below)
        if (ch < 63) {
            const int k0n = (ch + 1) * 32;
#pragma unroll
            for (int i = 0; i < 4; ++i) {
                apf[i] = *(const float4*)(Ab + (size_t)gr * 2048 + k0n + gk + i * 4);
                bpf[i] = *(const float4*)(Bb + (size_t)gr * 2048 + k0n + gk + i * 4);
            }
        }

        // ---- compute: 4 k-steps; fp32 fragment load, register hi/lo split ----
#pragma unroll
        for (int ks = 0; ks < 4; ++ks) {
            const int off = ks * 8 + tig;
            float ar[4][4], br[4][2];
#pragma unroll
            for (int mt = 0; mt < 4; ++mt) {
                const int r0 = (warp_m + mt * 16 + g) * G_LDS + off;
                ar[mt][0] = As[r0];
                ar[mt][1] = As[r0 + 8 * G_LDS];
                ar[mt][2] = As[r0 + 4];
                ar[mt][3] = As[r0 + 8 * G_LDS + 4];
            }
#pragma unroll
            for (int nt = 0; nt < 4; ++nt) {
                const int n0 = (warp_n + nt * 8 + g) * G_LDS + off;
                br[nt][0] = Bs[n0];
                br[nt][1] = Bs[n0 + 4];
            }
            uint32_t ahf[4][4], alf[4][4], bhf[4][2], blf[4][2];
#pragma unroll
            for (int mt = 0; mt < 4; ++mt)
#pragma unroll
                for (int q = 0; q < 4; ++q) {
                    const float h = tf32rna(ar[mt][q]);
                    ahf[mt][q] = __float_as_uint(h);
                    alf[mt][q] = __float_as_uint(tf32rna(ar[mt][q] - h));
                }
#pragma unroll
            for (int nt = 0; nt < 4; ++nt)
#pragma unroll
                for (int q = 0; q < 2; ++q) {
                    const float h = tf32rna(br[nt][q]);
                    bhf[nt][q] = __float_as_uint(h);
                    blf[nt][q] = __float_as_uint(tf32rna(br[nt][q] - h));
                }
#pragma unroll
            for (int mt = 0; mt < 4; ++mt)
#pragma unroll
                for (int nt = 0; nt < 4; ++nt) {
                    mma_tf32(c[mt][nt], ahf[mt], bhf[nt]);
                    mma_tf32(c[mt][nt], ahf[mt], blf[nt]);
                    mma_tf32(c[mt][nt], alf[mt], bhf[nt]);
                }
        }

        // ---- store prefetched chunk into the other stage (consumed pre-sync) ----
        if (ch < 63) {
            float* An = gsm + (size_t)(s ^ 1) * (2 * G_TILE_FLOATS);
            float* Bn = An + G_TILE_FLOATS;
#pragma unroll
            for (int i = 0; i < 4; ++i) {
                float4 va = apf[i];
                if (fixA) {
                    va.x = nn_fix(va.x); va.y = nn_fix(va.y);
                    va.z = nn_fix(va.z); va.w = nn_fix(va.w);
                }
                *(float4*)&An[sbase + 4 * i] = va;
                *(float4*)&Bn[sbase + 4 * i] = bpf[i];
            }
        }
    }

    // ---- epilogue ----
#pragma unroll
    for (int mt = 0; mt < 4; ++mt) {
        const int row0 = bm * 128 + warp_m + mt * 16 + g;
#pragma unroll
        for (int nt = 0; nt < 4; ++nt) {
            const int coln = warp_n + nt * 8 + 2 * tig;
            if (mode == 3) {
                float* d0 = Cext + (size_t)row0 * 2048 + bn * 128 + coln;
                float* d1 = Cext + (size_t)(row0 + 8) * 2048 + bn * 128 + coln;
                d0[0] = nn_fix(c[mt][nt][0]); d0[1] = nn_fix(c[mt][nt][1]);
                d1[0] = nn_fix(c[mt][nt][2]); d1[1] = nn_fix(c[mt][nt][3]);
            } else {
                float* Cg = (mode == 0) ? g_q : (mode == 1) ? g_k : g_v;
                float* base = Cg + (size_t)bn * (TSEQ * HDIM);
                *(float2*)&base[(size_t)row0 * HDIM + coln] =
                    make_float2(c[mt][nt][0], c[mt][nt][1]);
                *(float2*)&base[(size_t)(row0 + 8) * HDIM + coln] =
                    make_float2(c[mt][nt][2], c[mt][nt][3]);
            }
        }
    }
}

// ---------------- RoPE in-place on g_q, g_k ----------------------------------
__global__ void rope_kernel()
{
    const int t = blockIdx.x;      // 0..2047
    const int i = threadIdx.x;     // 0..63 (pair index)
    const float pw = (float)pow(10000.0, (double)(2 * i) / 128.0);
    const float inv = 1.0f / pw;
    const float freq = (float)t * inv;
    const float c = cosf(freq);
    const float s = sinf(freq);
#pragma unroll 4
    for (int h = 0; h < NHEAD; ++h) {
        float* q = g_q + ((size_t)(h * TSEQ + t)) * HDIM;
        float x1 = q[i], x2 = q[i + 64];
        q[i]      = __fadd_rn(__fmul_rn(x1, c), __fmul_rn(-x2, s));
        q[i + 64] = __fadd_rn(__fmul_rn(x2, c), __fmul_rn(x1, s));
        float* k = g_k + ((size_t)(h * TSEQ + t)) * HDIM;
        float y1 = k[i], y2 = k[i + 64];
        k[i]      = __fadd_rn(__fmul_rn(y1, c), __fmul_rn(-y2, s));
        k[i + 64] = __fadd_rn(__fmul_rn(y2, c), __fmul_rn(y1, s));
    }
}

// ---------------- threefry-2x32, PARTITIONABLE path --------------------------
__device__ __forceinline__ unsigned rotl32(unsigned x, int d) {
    return (x << d) | (x >> (32 - d));
}

__device__ float jax_uniform42_partitionable(int h)
{
    const unsigned k0 = 0u, k1 = 42u;
    const unsigned k2 = k0 ^ k1 ^ 0x1BD11BDAu;
    const unsigned ks[3] = { k0, k1, k2 };
    unsigned x0 = 0u + k0;              // counter hi = 0
    unsigned x1 = (unsigned)h + k1;     // counter lo = h
    const int rotA[4] = { 13, 15, 26, 6 };
    const int rotB[4] = { 17, 29, 16, 24 };
#pragma unroll
    for (int i = 0; i < 5; ++i) {
        const int* R = (i & 1) ? rotB : rotA;
#pragma unroll
        for (int j = 0; j < 4; ++j) {
            x0 += x1;
            x1 = rotl32(x1, R[j]);
            x1 ^= x0;
        }
        x0 += ks[(i + 1) % 3];
        x1 += ks[(i + 2) % 3] + (unsigned)(i + 1);
    }
    const unsigned bits = x0 ^ x1;
    return __uint_as_float((bits >> 9) | 0x3f800000u) - 1.0f;
}

// ---------------- last-row stats: p, bern, v_e per head ----------------------
__global__ void __launch_bounds__(256) lastrow_kernel()
{
    const int h = blockIdx.x;
    const int tid = threadIdx.x;
    __shared__ float qv[128];
    __shared__ float s[2048];
    __shared__ float red[256];
    __shared__ float red2[256];
    __shared__ float sh_scale;

    if (tid < 128) qv[tid] = g_q[((size_t)h * TSEQ + 2047) * HDIM + tid];
    __syncthreads();

    for (int k = tid; k < 2048; k += 256) {
        const bool keep = (k < 204) || (k >= 1229);
        float val = -INFINITY;
        if (keep) {
            const float4* kr = (const float4*)(g_k + ((size_t)h * TSEQ + k) * HDIM);
            const float4* q4 = (const float4*)qv;
            float dot = 0.0f;
#pragma unroll
            for (int d4 = 0; d4 < 32; ++d4) {
                float4 a = q4[d4]; float4 b = kr[d4];
                dot = fmaf(a.x, b.x, dot); dot = fmaf(a.y, b.y, dot);
                dot = fmaf(a.z, b.z, dot); dot = fmaf(a.w, b.w, dot);
            }
            val = dot / 11.313708498984760f;  // / sqrt(128)
        }
        s[k] = val;
    }
    __syncthreads();

    float lm = -INFINITY;
    for (int k = tid; k < 2048; k += 256) lm = fmaxf(lm, s[k]);
    red[tid] = lm;
    __syncthreads();
    for (int st = 128; st > 0; st >>= 1) {
        if (tid < st) red[tid] = fmaxf(red[tid], red[tid + st]);
        __syncthreads();
    }
    const float m = red[0];
    __syncthreads();

    float ls = 0.0f, lrS = 0.0f;
    for (int k = tid; k < 2048; k += 256) {
        if ((k < 204) || (k >= 1229)) {
            const float e = expf(s[k] - m);
            ls += e;
            if (k >= 1230) lrS += e;
        }
    }
    red[tid] = ls; red2[tid] = lrS;
    __syncthreads();
    for (int st = 128; st > 0; st >>= 1) {
        if (tid < st) { red[tid] += red[tid + st]; red2[tid] += red2[tid + st]; }
        __syncthreads();
    }
    if (tid == 0) {
        const float L = red[0], R = red2[0];
        const float Pev = expf(s[1229] - m) / L;
        const float mean = (R / L) / 818.0f + 1e-6f;
        float p = Pev / mean;
        if (isnan(p)) p = 0.0f;
        p = fminf(fmaxf(p, 0.0f), 1.0f);
        const float u = jax_uniform42_partitionable(h);
        sh_scale = (u < p) ? 1.0f : 0.0f;
    }
    __syncthreads();
    if (tid < 128)
        g_ve[h * HDIM + tid] =
            (g_v[((size_t)h * TSEQ + 1229) * HDIM + tid] * sh_scale) / 819.0f;
}

// ---------------- flash-style attention over kept K columns ------------------
// (R5 scalar version — proven fastest FFMA formulation)
#define ATTN_SMEM_FLOATS (64*129 + 64*129 + 64*132 + 64*66 + 256)
#define ATTN_SMEM_BYTES  (ATTN_SMEM_FLOATS * 4)

__global__ void __launch_bounds__(256) attn_kernel()
{
    extern __shared__ float sm[];
    float* Qs   = sm;
    float* Ks   = Qs + 64 * 129;
    float* Vs   = Ks + 64 * 129;
    float* S    = Vs + 64 * 132;
    float* m_s  = S + 64 * 66;
    float* l_s  = m_s + 64;
    float* lr_s = l_s + 64;
    float* fac_s = lr_s + 64;

    const int h   = blockIdx.y;
    const int qt  = blockIdx.x;
    const int tid = threadIdx.x;
    const int ty  = tid >> 4;
    const int tx  = tid & 15;
    const int r0  = ty << 2;
    const int cS0 = tx << 2;
    const int cV0 = tx << 3;

    const int ldr = tid >> 5;
    const int ldc = (tid & 31) << 2;

    const float* qbase = g_q + ((size_t)h * TSEQ + qt * 64) * HDIM;
#pragma unroll
    for (int it = 0; it < 8; ++it) {
        const int j = ldr + it * 8;
        float4 v = *(const float4*)(qbase + (size_t)j * HDIM + ldc);
        Qs[j * 129 + ldc + 0] = v.x; Qs[j * 129 + ldc + 1] = v.y;
        Qs[j * 129 + ldc + 2] = v.z; Qs[j * 129 + ldc + 3] = v.w;
    }
    if (tid < 64) { m_s[tid] = -INFINITY; l_s[tid] = 0.0f; lr_s[tid] = 0.0f; }

    float acc[4][8];
#pragma unroll
    for (int i = 0; i < 4; ++i)
#pragma unroll
        for (int j = 0; j < 8; ++j) acc[i][j] = 0.0f;

    __syncthreads();

    for (int tile = 0; tile < 17; ++tile) {
        const int kb   = (tile < 4) ? tile * 64 : 1229 + (tile - 4) * 64;
        const int kend = (tile < 4) ? 204 : 2048;

#pragma unroll
        for (int it = 0; it < 8; ++it) {
            const int j = ldr + it * 8;
            const int kc = kb + j;
            float4 kv = make_float4(0.f, 0.f, 0.f, 0.f);
            float4 vv = kv;
            if (kc < kend) {
                kv = *(const float4*)(g_k + ((size_t)h * TSEQ + kc) * HDIM + ldc);
                vv = *(const float4*)(g_v + ((size_t)h * TSEQ + kc) * HDIM + ldc);
            }
            Ks[j * 129 + ldc + 0] = kv.x; Ks[j * 129 + ldc + 1] = kv.y;
            Ks[j * 129 + ldc + 2] = kv.z; Ks[j * 129 + ldc + 3] = kv.w;
            *(float4*)&Vs[j * 132 + ldc] = vv;
        }
        __syncthreads();

        float sacc[4][4];
#pragma unroll
        for (int i = 0; i < 4; ++i)
#pragma unroll
            for (int j = 0; j < 4; ++j) sacc[i][j] = 0.0f;

        const float* q0 = Qs + (r0 + 0) * 129;
        const float* q1 = Qs + (r0 + 1) * 129;
        const float* q2 = Qs + (r0 + 2) * 129;
        const float* q3 = Qs + (r0 + 3) * 129;
        const float* kp0 = Ks + (cS0 + 0) * 129;
        const float* kp1 = Ks + (cS0 + 1) * 129;
        const float* kp2 = Ks + (cS0 + 2) * 129;
        const float* kp3 = Ks + (cS0 + 3) * 129;
#pragma unroll 8
        for (int kk = 0; kk < 128; ++kk) {
            const float a0 = q0[kk], a1 = q1[kk], a2 = q2[kk], a3 = q3[kk];
            const float b0 = kp0[kk], b1 = kp1[kk], b2 = kp2[kk], b3 = kp3[kk];
            sacc[0][0] = fmaf(a0, b0, sacc[0][0]); sacc[0][1] = fmaf(a0, b1, sacc[0][1]);
            sacc[0][2] = fmaf(a0, b2, sacc[0][2]); sacc[0][3] = fmaf(a0, b3, sacc[0][3]);
            sacc[1][0] = fmaf(a1, b0, sacc[1][0]); sacc[1][1] = fmaf(a1, b1, sacc[1][1]);
            sacc[1][2] = fmaf(a1, b2, sacc[1][2]); sacc[1][3] = fmaf(a1, b3, sacc[1][3]);
            sacc[2][0] = fmaf(a2, b0, sacc[2][0]); sacc[2][1] = fmaf(a2, b1, sacc[2][1]);
            sacc[2][2] = fmaf(a2, b2, sacc[2][2]); sacc[2][3] = fmaf(a2, b3, sacc[2][3]);
            sacc[3][0] = fmaf(a3, b0, sacc[3][0]); sacc[3][1] = fmaf(a3, b1, sacc[3][1]);
            sacc[3][2] = fmaf(a3, b2, sacc[3][2]); sacc[3][3] = fmaf(a3, b3, sacc[3][3]);
        }
#pragma unroll
        for (int i = 0; i < 4; ++i)
#pragma unroll
            for (int j = 0; j < 4; ++j) {
                const int kc = kb + cS0 + j;
                S[(r0 + i) * 66 + cS0 + j] =
                    (kc < kend) ? sacc[i][j] / 11.313708498984760f : -1e30f;
            }
        __syncthreads();

        if (tid < 64) {
            const int r = tid;
            float* Sr = S + r * 66;
            float tm = -1e30f;
#pragma unroll 8
            for (int j = 0; j < 64; ++j) tm = fmaxf(tm, Sr[j]);
            const float mo = m_s[r];
            const float mn = fmaxf(mo, tm);
            const float fac = expf(mo - mn);
            float sum = 0.0f, sumr = 0.0f;
#pragma unroll 4
            for (int j = 0; j < 64; ++j) {
                const float e = expf(Sr[j] - mn);
                Sr[j] = e;
                sum += e;
                if (kb + j >= 1230) sumr += e;
            }
            l_s[r]  = l_s[r]  * fac + sum;
            lr_s[r] = lr_s[r] * fac + sumr;
            m_s[r]  = mn;
            fac_s[r] = fac;
        }
        __syncthreads();

        {
            const float f0 = fac_s[r0 + 0], f1 = fac_s[r0 + 1];
            const float f2 = fac_s[r0 + 2], f3 = fac_s[r0 + 3];
#pragma unroll
            for (int j = 0; j < 8; ++j) {
                acc[0][j] *= f0; acc[1][j] *= f1; acc[2][j] *= f2; acc[3][j] *= f3;
            }
        }
#pragma unroll 2
        for (int jp = 0; jp < 64; ++jp) {
            const float p0 = S[(r0 + 0) * 66 + jp];
            const float p1 = S[(r0 + 1) * 66 + jp];
            const float p2 = S[(r0 + 2) * 66 + jp];
            const float p3 = S[(r0 + 3) * 66 + jp];
            float vv[8];
            *(float4*)&vv[0] = *(const float4*)&Vs[jp * 132 + cV0];
            *(float4*)&vv[4] = *(const float4*)&Vs[jp * 132 + cV0 + 4];
#pragma unroll
            for (int j = 0; j < 8; ++j) {
                acc[0][j] = fmaf(p0, vv[j], acc[0][j]);
                acc[1][j] = fmaf(p1, vv[j], acc[1][j]);
                acc[2][j] = fmaf(p2, vv[j], acc[2][j]);
                acc[3][j] = fmaf(p3, vv[j], acc[3][j]);
            }
        }
        __syncthreads();
    }

    const int qg0 = qt * 64;
#pragma unroll
    for (int i = 0; i < 4; ++i) {
        const int r = r0 + i;
        const int qrow = qg0 + r;
        const float linv = 1.0f / l_s[r];
        const float corr = (qrow >= 1792) ? lr_s[r] * linv : 0.0f;
#pragma unroll
        for (int j = 0; j < 8; ++j) {
            const int dcol = cV0 + j;
            const float o = acc[i][j] * linv + corr * g_ve[h * HDIM + dcol];
            g_ctx[(size_t)qrow * 2048 + h * HDIM + dcol] = o;
        }
    }
}

// ---------------- launch ------------------------------------------------------
extern "C" void kernel_launch(void* const* d_in, const int* in_sizes, int n_in,
                              void* d_out, int out_size)
{
    (void)in_sizes; (void)n_in; (void)out_size;
    const float* hs = (const float*)d_in[0];
    const float* Wq = (const float*)d_in[1];
    const float* Wk = (const float*)d_in[2];
    const float* Wv = (const float*)d_in[3];
    const float* Wo = (const float*)d_in[4];
    float* out = (float*)d_out;

    cudaFuncSetAttribute(gemm_tc_kernel,
                         cudaFuncAttributeMaxDynamicSharedMemorySize,
                         G_SMEM_BYTES);
    cudaFuncSetAttribute(attn_kernel,
                         cudaFuncAttributeMaxDynamicSharedMemorySize,
                         ATTN_SMEM_BYTES);

    dim3 ggrid(16, 16);
    gemm_tc_kernel<<<ggrid, 256, G_SMEM_BYTES>>>(hs, Wq, nullptr, 0);
    gemm_tc_kernel<<<ggrid, 256, G_SMEM_BYTES>>>(hs, Wk, nullptr, 1);
    gemm_tc_kernel<<<ggrid, 256, G_SMEM_BYTES>>>(hs, Wv, nullptr, 2);
    rope_kernel<<<2048, 64>>>();
    lastrow_kernel<<<16, 256>>>();
    attn_kernel<<<dim3(32, 16), 256, ATTN_SMEM_BYTES>>>();
    gemm_tc_kernel<<<ggrid, 256, G_SMEM_BYTES>>>(nullptr, Wo, out, 3);
}